// round 14
// baseline (speedup 1.0000x reference)
#include <cuda_runtime.h>
#include <cstdint>

#define BB  4
#define SS  2048
#define DD  768
#define NHH 4
#define DHH 192
#define KW  4

// ---------------- scratch (device globals; no allocation allowed) ----------------
__device__ float g_XC[(size_t)BB * SS * DD];                    // conv+swish output
__device__ float g_G[(size_t)BB * NHH * 4 * SS * DHH];          // gate preactivations [b][h][g][s][e]
__device__ float g_Y[(size_t)BB * SS * DD];                     // scan output (pre-LN)

// ---------------- small PTX helpers ----------------
__device__ __forceinline__ unsigned smem_u32(const void* p) {
    return (unsigned)__cvta_generic_to_shared(p);
}
__device__ __forceinline__ unsigned mapa_sh(unsigned addr, unsigned rank) {
    unsigned r;
    asm("mapa.shared::cluster.u32 %0, %1, %2;" : "=r"(r) : "r"(addr), "r"(rank));
    return r;
}
// single 8B relaxed store to a (possibly remote) cluster smem address
__device__ __forceinline__ void st_pair_cluster(unsigned addr, unsigned long long p) {
    asm volatile("st.relaxed.cluster.shared::cluster.b64 [%0], %1;"
                 :: "r"(addr), "l"(p) : "memory");
}
// 8B relaxed load from local smem
__device__ __forceinline__ unsigned long long ld_pair(unsigned addr) {
    unsigned long long p;
    asm volatile("ld.relaxed.cluster.shared::cta.b64 %0, [%1];"
                 : "=l"(p) : "r"(addr) : "memory");
    return p;
}
__device__ __forceinline__ void cluster_sync_all() {
    asm volatile("barrier.cluster.arrive.aligned;" ::: "memory");
    asm volatile("barrier.cluster.wait.aligned;" ::: "memory");
}
// packed dual fp32 FMA (Blackwell f32x2)
__device__ __forceinline__ float2 ffma2(float2 a, float2 b, float2 c) {
    float2 d;
    asm("fma.rn.f32x2 %0, %1, %2, %3;"
        : "=l"(reinterpret_cast<unsigned long long&>(d))
        : "l"(reinterpret_cast<unsigned long long&>(a)),
          "l"(reinterpret_cast<unsigned long long&>(b)),
          "l"(reinterpret_cast<unsigned long long&>(c)));
    return d;
}
// duplicate a scalar into both halves of an f32x2
__device__ __forceinline__ float2 dup2(float a) {
    float2 d;
    asm("mov.b64 %0, {%1, %1};"
        : "=l"(reinterpret_cast<unsigned long long&>(d)) : "f"(a));
    return d;
}

// ---------------- 1) causal depthwise conv + swish ----------------
__global__ __launch_bounds__(256) void conv_swish_kernel(
    const float* __restrict__ X, const float* __restrict__ CK, const float* __restrict__ CB)
{
    int idx = blockIdx.x * 256 + threadIdx.x;
    if (idx >= BB * SS * DD) return;
    int d  = idx % DD;
    int bs = idx / DD;
    int s  = bs % SS;
    float acc = CB[d];
#pragma unroll
    for (int j = 0; j < KW; j++) {
        int sp = s + j - (KW - 1);
        if (sp >= 0) acc = fmaf(CK[j * DD + d], X[idx + (j - (KW - 1)) * DD], acc);
    }
    g_XC[idx] = acc / (1.f + __expf(-acc));   // swish
}

// ---------------- 2) gate projections: 64 GEMMs (2048x192 @ 192x192) ----------------
#define GBM 128
#define GBN 96
#define GBK 32
#define AS_STRIDE 129   // padded: conflict-free STS, broadcast LDS

__global__ __launch_bounds__(256) void gemm_gates_kernel(
    const float* __restrict__ X,
    const float* __restrict__ Wi, const float* __restrict__ Wf,
    const float* __restrict__ Wz, const float* __restrict__ Wo)
{
    __shared__ float As[GBK * AS_STRIDE];
    __shared__ float Bs[GBK][GBN];

    int z = blockIdx.z;               // b*16 + h*4 + g
    int b = z >> 4, h = (z >> 2) & 3, g = z & 3;
    int m0 = blockIdx.x * GBM;
    int n0 = blockIdx.y * GBN;

    const float* A = ((g < 2) ? g_XC : X) + (size_t)b * SS * DD + h * DHH;  // row stride DD
    const float* W = ((g == 0) ? Wi : (g == 1) ? Wf : (g == 2) ? Wz : Wo) + (size_t)h * DHH * DHH;
    float* C = g_G + (size_t)z * SS * DHH;

    int tid = threadIdx.x;
    int tm = (tid >> 4) * 8;          // 16 groups x 8 rows
    int tn = (tid & 15) * 6;          // 16 groups x 6 cols

    float2 acc[8][3];
#pragma unroll
    for (int i = 0; i < 8; i++)
#pragma unroll
        for (int j = 0; j < 3; j++) acc[i][j] = make_float2(0.f, 0.f);

    for (int k0 = 0; k0 < DHH; k0 += GBK) {
        // load A tile 128x32 (float4, coalesced), store transposed As[k][m]
#pragma unroll
        for (int t = 0; t < 4; t++) {
            int i4 = t * 256 + tid;
            int m = i4 >> 3, kq = i4 & 7;
            float4 v = *(const float4*)(A + (size_t)(m0 + m) * DD + k0 + kq * 4);
            As[(kq * 4 + 0) * AS_STRIDE + m] = v.x;
            As[(kq * 4 + 1) * AS_STRIDE + m] = v.y;
            As[(kq * 4 + 2) * AS_STRIDE + m] = v.z;
            As[(kq * 4 + 3) * AS_STRIDE + m] = v.w;
        }
        // load B tile 32x96 (float4)
#pragma unroll
        for (int t = 0; t < 3; t++) {
            int i4 = t * 256 + tid;
            int kk = i4 / 24, nq = i4 % 24;
            float4 v = *(const float4*)(W + (size_t)(k0 + kk) * DHH + n0 + nq * 4);
            *(float4*)&Bs[kk][nq * 4] = v;
        }
        __syncthreads();
#pragma unroll
        for (int k = 0; k < GBK; k++) {
            float2 b2[3];
#pragma unroll
            for (int j = 0; j < 3; j++) b2[j] = *(const float2*)&Bs[k][tn + 2 * j];
#pragma unroll
            for (int i = 0; i < 8; i++) {
                float2 ad = dup2(As[k * AS_STRIDE + tm + i]);
#pragma unroll
                for (int j = 0; j < 3; j++) acc[i][j] = ffma2(ad, b2[j], acc[i][j]);
            }
        }
        __syncthreads();
    }
#pragma unroll
    for (int i = 0; i < 8; i++)
#pragma unroll
        for (int j = 0; j < 3; j++)
            *(float2*)(C + (size_t)(m0 + tm + i) * DHH + n0 + tn + 2 * j) = acc[i][j];
}

// ---------------- 3) sequential sLSTM scan ----------------
// 16 clusters of 8 CTAs; cluster = one (b,h). CTA rank r owns output slice
// e in [r*24, r*24+24) of ALL four gates. h exchanged via DSMEM as tagged
// 8-byte {value, step} pairs (single-copy atomic). Thread (e_loc, chunk)
// computes partials of all 4 gates over a 12-wide k chunk; a 4-round
// shfl.xor reduction leaves all 4 gate preactivations in the chunk-0 lane,
// so gating runs in registers: ONE __syncthreads per step, no sh_pre.
#define NCH 16          // k chunks per element
#define CHK 12          // k per chunk
#define CHSTRIDE 20     // floats per chunk slot in sh_h (12 used + 8 pad)
                        // bases 80c bytes: distinct multiples of 16 mod 256
                        // -> each LDS.128 is minimal 2 wavefronts

__global__ __launch_bounds__(384, 1) __cluster_dims__(8, 1, 1)
void scan_kernel(const float* __restrict__ R, const float* __restrict__ CBIAS)
{
    __shared__ __align__(16) float2 hpair[2][DHH];            // transport: {value, tag}
    __shared__ __align__(16) float sh_h[2][NCH * CHSTRIDE];   // compute: chunked h values

    int tid = threadIdx.x;
    int cid = blockIdx.x >> 3;     // (b*NH + h)
    int b = cid >> 2;
    int h = cid & 3;
    int r = blockIdx.x & 7;        // cluster rank (8 CTAs)
    int e0 = r * 24;

    int e_loc  = tid >> 4;         // 0..23 : local output element
    int chunk  = tid & 15;         // 0..15 : k chunk of 12
    int eg     = e0 + e_loc;       // element within head
    int k0r    = chunk * CHK;      // first k of this chunk

    // register-resident recurrent weights: per gate, 6 k-pairs of this chunk
    // w[g*6+p] = {R_g[k0r+2p][eg], R_g[k0r+2p+1][eg]}
    float2 w[24];
#pragma unroll
    for (int g = 0; g < 4; g++) {
        const float* Rb = R + ((size_t)(g * NHH + h)) * DHH * DHH + eg;
#pragma unroll
        for (int p = 0; p < 6; p++) {
            w[g * 6 + p].x = Rb[(size_t)(k0r + 2 * p) * DHH];
            w[g * 6 + p].y = Rb[(size_t)(k0r + 2 * p + 1) * DHH];
        }
    }
    // gate preactivation stream + bias: handled by chunk<4 lanes (gate = chunk)
    const float* gptr = g_G + ((size_t)(cid * 4 + (chunk & 3))) * SS * DHH + eg;
    float bv = CBIAS[(chunk & 3) * DD + h * DHH + eg];

    float* ybase = g_Y + (size_t)b * SS * DD + h * DHH;

    // per-thread scan state (only meaningful for chunk==0 lanes)
    float c_r = 0.f, n_r = 0.f, m_r = 0.f;

    // init transport: value 0, tag 0  (tag 0 == h_0)
    for (int i = tid; i < DHH; i += 384) {
        hpair[0][i] = make_float2(0.f, __uint_as_float(0u));
        hpair[1][i] = make_float2(0.f, __uint_as_float(0u));
    }

    // producers (chunk==0): remote pair addresses for element eg on all 8 ranks
    unsigned pa[8];
    if (chunk == 0) {
        unsigned a0 = smem_u32(&hpair[0][eg]);
#pragma unroll
        for (int i = 0; i < 8; i++) pa[i] = mapa_sh(a0, (unsigned)i);
    }
    // consumers: thread t (<192) polls pair t, stages into chunked slot
    int cslot = (tid / CHK) * CHSTRIDE + (tid % CHK);
    unsigned poll_a = smem_u32(&hpair[0][tid < DHH ? tid : 0]);

    __syncthreads();
    cluster_sync_all();   // zeroed tagged buffers visible cluster-wide

    // 2-deep gate-preactivation prefetch (load-to-use > DRAM latency)
    float g0 = 0.f, g1 = 0.f;
    if (chunk < 4) { g0 = gptr[0]; g1 = gptr[DHH]; }

    const unsigned BUFBYTES = DHH * 8;

    for (int s = 0; s < SS; s++) {
        int cur = s & 1;

        // ---- wait for h_s (tag >= s) and stage value into chunked array ----
        if (tid < DHH) {
            unsigned a = poll_a + (unsigned)cur * BUFBYTES;
            unsigned long long p = ld_pair(a);
            while ((unsigned)(p >> 32) < (unsigned)s) p = ld_pair(a);
            sh_h[cur][cslot] = __uint_as_float((unsigned)p);
        }
        __syncthreads();                                  // all h_s values staged

        float g2 = 0.f;
        if (chunk < 4) {
            int sp = (s + 2 < SS) ? s + 2 : SS - 1;
            g2 = gptr[(size_t)sp * DHH];
        }

        // ---- chunk matvec: 12 h values, partials for all 4 gates ----
        const float4* hp = (const float4*)&sh_h[cur][chunk * CHSTRIDE];
        float4 h0 = hp[0], h1 = hp[1], h2v = hp[2];
        float2 hh[6];
        hh[0] = make_float2(h0.x, h0.y);  hh[1] = make_float2(h0.z, h0.w);
        hh[2] = make_float2(h1.x, h1.y);  hh[3] = make_float2(h1.z, h1.w);
        hh[4] = make_float2(h2v.x, h2v.y); hh[5] = make_float2(h2v.z, h2v.w);

        float pg[4];
#pragma unroll
        for (int g = 0; g < 4; g++) {
            float2 a2 = make_float2(0.f, 0.f), b2 = a2;
            a2 = ffma2(hh[0], w[g * 6 + 0], a2);
            b2 = ffma2(hh[1], w[g * 6 + 1], b2);
            a2 = ffma2(hh[2], w[g * 6 + 2], a2);
            b2 = ffma2(hh[3], w[g * 6 + 3], b2);
            a2 = ffma2(hh[4], w[g * 6 + 4], a2);
            b2 = ffma2(hh[5], w[g * 6 + 5], b2);
            pg[g] = (a2.x + b2.x) + (a2.y + b2.y);
            if (chunk == g) pg[g] += g0 + bv;             // fold gpre+bias pre-reduce
        }
        g0 = g1; g1 = g2;

        // ---- reduce over 16 chunk lanes (xor masks stay within e group) ----
#pragma unroll
        for (int g = 0; g < 4; g++) {
            pg[g] += __shfl_xor_sync(0xffffffffu, pg[g], 1);
            pg[g] += __shfl_xor_sync(0xffffffffu, pg[g], 2);
            pg[g] += __shfl_xor_sync(0xffffffffu, pg[g], 4);
            pg[g] += __shfl_xor_sync(0xffffffffu, pg[g], 8);
        }

        // ---- gating in registers (chunk-0 lane owns element eg) ----
        if (chunk == 0) {
            float it = pg[0], ft = pg[1], zt = pg[2], ot = pg[3];
            float fm = ft + m_r;
            float mn = fmaxf(fm, it);
            float ia = __expf(it - mn);
            float fa = __expf(fm - mn);
            float th = 1.f - 2.f / (__expf(2.f * zt) + 1.f);       // tanh
            float cn = fa * c_r + ia * th;
            float nn = fa * n_r + ia;
            float hv = cn / ((1.f + __expf(-ot)) * nn);            // sigmoid(ot)*cn/nn
            c_r = cn; n_r = nn; m_r = mn;

            // ship {value, tag=s+1} as one atomic 8B store to all 8 ranks
            unsigned long long p =
                ((unsigned long long)(unsigned)(s + 1) << 32) | (unsigned long long)__float_as_uint(hv);
            unsigned off = (unsigned)((s + 1) & 1) * BUFBYTES;
#pragma unroll
            for (int i = 0; i < 8; i++) st_pair_cluster(pa[i] + off, p);

            ybase[(size_t)s * DD + eg] = hv;          // pre-LN output
        }
        // no trailing bar: next iteration's poll+bar provides the sync
    }

    cluster_sync_all();   // don't exit while peer stores may be in flight
}

// ---------------- 4) multi-head layernorm ----------------
__global__ __launch_bounds__(256) void ln_kernel(const float* __restrict__ GS, float* __restrict__ OUT)
{
    int w = blockIdx.x * 8 + (threadIdx.x >> 5);   // (b*S+s)*NH + h
    int lane = threadIdx.x & 31;
    int h = w & 3;
    int bs = w >> 2;
    const float* yp = g_Y + (size_t)bs * DD + h * DHH;

    float v[6], sum = 0.f, sq = 0.f;
#pragma unroll
    for (int i = 0; i < 6; i++) {
        v[i] = yp[i * 32 + lane];
        sum += v[i];
        sq  = fmaf(v[i], v[i], sq);
    }
#pragma unroll
    for (int o = 16; o > 0; o >>= 1) {
        sum += __shfl_xor_sync(0xffffffffu, sum, o);
        sq  += __shfl_xor_sync(0xffffffffu, sq,  o);
    }
    float mean = sum * (1.f / 192.f);
    float var  = sq * (1.f / 192.f) - mean * mean;
    float inv  = rsqrtf(var + 1e-5f);
    float* op = OUT + (size_t)bs * DD + h * DHH;
#pragma unroll
    for (int i = 0; i < 6; i++)
        op[i * 32 + lane] = (v[i] - mean) * inv * GS[h * DHH + i * 32 + lane];
}

// ---------------- launch ----------------
extern "C" void kernel_launch(void* const* d_in, const int* in_sizes, int n_in,
                              void* d_out, int out_size)
{
    const float* x     = (const float*)d_in[0];
    const float* ck    = (const float*)d_in[1];
    const float* cb    = (const float*)d_in[2];
    const float* Wi    = (const float*)d_in[3];
    const float* Wf    = (const float*)d_in[4];
    const float* Wz    = (const float*)d_in[5];
    const float* Wo    = (const float*)d_in[6];
    const float* R     = (const float*)d_in[7];
    const float* cbias = (const float*)d_in[8];
    const float* gs    = (const float*)d_in[9];
    float* out = (float*)d_out;

    conv_swish_kernel<<<(BB * SS * DD + 255) / 256, 256>>>(x, ck, cb);
    gemm_gates_kernel<<<dim3(SS / GBM, DHH / GBN, BB * NHH * 4), 256>>>(x, Wi, Wf, Wz, Wo);
    scan_kernel<<<BB * NHH * 8, 384>>>(R, cbias);
    ln_kernel<<<(BB * SS * NHH) / 8, 256>>>(gs, out);
}

// round 15
// speedup vs baseline: 1.7658x; 1.7658x over previous
#include <cuda_runtime.h>
#include <cstdint>

#define BB  4
#define SS  2048
#define DD  768
#define NHH 4
#define DHH 192
#define KW  4

// ---------------- scratch (device globals; no allocation allowed) ----------------
__device__ float g_XC[(size_t)BB * SS * DD];                    // conv+swish output
__device__ float g_G[(size_t)BB * NHH * 4 * SS * DHH];          // gate preactivations [b][h][g][s][e]
__device__ float g_Y[(size_t)BB * SS * DD];                     // scan output (pre-LN)

// ---------------- small PTX helpers ----------------
__device__ __forceinline__ unsigned smem_u32(const void* p) {
    return (unsigned)__cvta_generic_to_shared(p);
}
__device__ __forceinline__ unsigned mapa_sh(unsigned addr, unsigned rank) {
    unsigned r;
    asm("mapa.shared::cluster.u32 %0, %1, %2;" : "=r"(r) : "r"(addr), "r"(rank));
    return r;
}
// single 8B relaxed store to a (possibly remote) cluster smem address
__device__ __forceinline__ void st_pair_cluster(unsigned addr, unsigned long long p) {
    asm volatile("st.relaxed.cluster.shared::cluster.b64 [%0], %1;"
                 :: "r"(addr), "l"(p) : "memory");
}
// 8B relaxed load from local smem
__device__ __forceinline__ unsigned long long ld_pair(unsigned addr) {
    unsigned long long p;
    asm volatile("ld.relaxed.cluster.shared::cta.b64 %0, [%1];"
                 : "=l"(p) : "r"(addr) : "memory");
    return p;
}
__device__ __forceinline__ void cluster_sync_all() {
    asm volatile("barrier.cluster.arrive.aligned;" ::: "memory");
    asm volatile("barrier.cluster.wait.aligned;" ::: "memory");
}
// packed dual fp32 FMA (Blackwell f32x2)
__device__ __forceinline__ float2 ffma2(float2 a, float2 b, float2 c) {
    float2 d;
    asm("fma.rn.f32x2 %0, %1, %2, %3;"
        : "=l"(reinterpret_cast<unsigned long long&>(d))
        : "l"(reinterpret_cast<unsigned long long&>(a)),
          "l"(reinterpret_cast<unsigned long long&>(b)),
          "l"(reinterpret_cast<unsigned long long&>(c)));
    return d;
}
// duplicate a scalar into both halves of an f32x2
__device__ __forceinline__ float2 dup2(float a) {
    float2 d;
    asm("mov.b64 %0, {%1, %1};"
        : "=l"(reinterpret_cast<unsigned long long&>(d)) : "f"(a));
    return d;
}

// ---------------- 1) causal depthwise conv + swish ----------------
__global__ __launch_bounds__(256) void conv_swish_kernel(
    const float* __restrict__ X, const float* __restrict__ CK, const float* __restrict__ CB)
{
    int idx = blockIdx.x * 256 + threadIdx.x;
    if (idx >= BB * SS * DD) return;
    int d  = idx % DD;
    int bs = idx / DD;
    int s  = bs % SS;
    float acc = CB[d];
#pragma unroll
    for (int j = 0; j < KW; j++) {
        int sp = s + j - (KW - 1);
        if (sp >= 0) acc = fmaf(CK[j * DD + d], X[idx + (j - (KW - 1)) * DD], acc);
    }
    g_XC[idx] = acc / (1.f + __expf(-acc));   // swish
}

// ---------------- 2) gate projections: 64 GEMMs (2048x192 @ 192x192) ----------------
#define GBM 128
#define GBN 96
#define GBK 32
#define AS_STRIDE 129   // padded: conflict-free STS, broadcast LDS

__global__ __launch_bounds__(256) void gemm_gates_kernel(
    const float* __restrict__ X,
    const float* __restrict__ Wi, const float* __restrict__ Wf,
    const float* __restrict__ Wz, const float* __restrict__ Wo)
{
    __shared__ float As[GBK * AS_STRIDE];
    __shared__ float Bs[GBK][GBN];

    int z = blockIdx.z;               // b*16 + h*4 + g
    int b = z >> 4, h = (z >> 2) & 3, g = z & 3;
    int m0 = blockIdx.x * GBM;
    int n0 = blockIdx.y * GBN;

    const float* A = ((g < 2) ? g_XC : X) + (size_t)b * SS * DD + h * DHH;  // row stride DD
    const float* W = ((g == 0) ? Wi : (g == 1) ? Wf : (g == 2) ? Wz : Wo) + (size_t)h * DHH * DHH;
    float* C = g_G + (size_t)z * SS * DHH;

    int tid = threadIdx.x;
    int tm = (tid >> 4) * 8;          // 16 groups x 8 rows
    int tn = (tid & 15) * 6;          // 16 groups x 6 cols

    float2 acc[8][3];
#pragma unroll
    for (int i = 0; i < 8; i++)
#pragma unroll
        for (int j = 0; j < 3; j++) acc[i][j] = make_float2(0.f, 0.f);

    for (int k0 = 0; k0 < DHH; k0 += GBK) {
        // load A tile 128x32 (float4, coalesced), store transposed As[k][m]
#pragma unroll
        for (int t = 0; t < 4; t++) {
            int i4 = t * 256 + tid;
            int m = i4 >> 3, kq = i4 & 7;
            float4 v = *(const float4*)(A + (size_t)(m0 + m) * DD + k0 + kq * 4);
            As[(kq * 4 + 0) * AS_STRIDE + m] = v.x;
            As[(kq * 4 + 1) * AS_STRIDE + m] = v.y;
            As[(kq * 4 + 2) * AS_STRIDE + m] = v.z;
            As[(kq * 4 + 3) * AS_STRIDE + m] = v.w;
        }
        // load B tile 32x96 (float4)
#pragma unroll
        for (int t = 0; t < 3; t++) {
            int i4 = t * 256 + tid;
            int kk = i4 / 24, nq = i4 % 24;
            float4 v = *(const float4*)(W + (size_t)(k0 + kk) * DHH + n0 + nq * 4);
            *(float4*)&Bs[kk][nq * 4] = v;
        }
        __syncthreads();
#pragma unroll
        for (int k = 0; k < GBK; k++) {
            float2 b2[3];
#pragma unroll
            for (int j = 0; j < 3; j++) b2[j] = *(const float2*)&Bs[k][tn + 2 * j];
#pragma unroll
            for (int i = 0; i < 8; i++) {
                float2 ad = dup2(As[k * AS_STRIDE + tm + i]);
#pragma unroll
                for (int j = 0; j < 3; j++) acc[i][j] = ffma2(ad, b2[j], acc[i][j]);
            }
        }
        __syncthreads();
    }
#pragma unroll
    for (int i = 0; i < 8; i++)
#pragma unroll
        for (int j = 0; j < 3; j++)
            *(float2*)(C + (size_t)(m0 + tm + i) * DHH + n0 + tn + 2 * j) = acc[i][j];
}

// ---------------- 3) sequential sLSTM scan ----------------
// 16 clusters of 4 CTAs; cluster = one (b,h). CTA rank r owns output slice
// e in [r*48, r*48+48) of ALL four gates. h exchanged via DSMEM as tagged
// 8-byte {value, step} pairs (single-copy atomic). Warp-local layout:
// lane = g*8 + kh*4 + e4; warp w owns elements 4w..4w+3. After the matvec,
// shfl.xor(4) combines k-halves and 4x shfl.idx gathers all four gate
// preactivations into lanes 0-3, which run gating in REGISTERS.
// -> ONE __syncthreads per step, no sh_pre staging.
#define HPAD 100   // float offset of kh=1 half in compact array (96 + 4 pad)

__global__ __launch_bounds__(384, 1) __cluster_dims__(4, 1, 1)
void scan_kernel(const float* __restrict__ R, const float* __restrict__ CBIAS)
{
    __shared__ __align__(16) float2 hpair[2][DHH];    // transport: {value, tag}
    __shared__ __align__(16) float sh_h[2][2 * HPAD]; // compute: compact values, padded halves

    int tid = threadIdx.x;
    int cid = blockIdx.x >> 2;     // (b*NH + h)
    int b = cid >> 2;
    int h = cid & 3;
    int r = blockIdx.x & 3;        // cluster rank
    int e0 = r * 48;

    int lane = tid & 31;
    int wrp  = tid >> 5;           // 0..11
    int g    = lane >> 3;          // 0..3 gate
    int kh   = (lane >> 2) & 1;    // 0..1 k half
    int e4   = lane & 3;           // 0..3 element within warp group
    int el   = (wrp << 2) | e4;    // 0..47 local element
    int eg   = e0 + el;            // element within head
    int kbase = kh * 96;           // first k of this half

    // register-resident recurrent weights: pairs {R_g[kbase+2i][eg], R_g[kbase+2i+1][eg]}
    float2 w[48];
    {
        const float* Rb = R + ((size_t)(g * NHH + h)) * DHH * DHH + eg;
#pragma unroll
        for (int i = 0; i < 48; i++) {
            w[i].x = Rb[(size_t)(kbase + 2 * i) * DHH];
            w[i].y = Rb[(size_t)(kbase + 2 * i + 1) * DHH];
        }
    }
    float bv = CBIAS[g * DD + h * DHH + eg];

    const float* gptr = g_G + ((size_t)(cid * 4 + g)) * SS * DHH + eg;
    float* ybase = g_Y + (size_t)b * SS * DD + h * DHH;

    // per-thread scan state (only meaningful for lanes 0-3 of each warp)
    float c_r = 0.f, n_r = 0.f, m_r = 0.f;

    // init transport: value 0, tag 0  (tag 0 == h_0)
    for (int i = tid; i < DHH; i += 384) {
        hpair[0][i] = make_float2(0.f, __uint_as_float(0u));
        hpair[1][i] = make_float2(0.f, __uint_as_float(0u));
    }

    // producers (lanes 0-3): remote pair addresses for element eg on all 4 ranks
    unsigned pa0 = 0, pa1 = 0, pa2 = 0, pa3 = 0;
    if (lane < 4) {
        unsigned a0 = smem_u32(&hpair[0][eg]);
        pa0 = mapa_sh(a0, 0);
        pa1 = mapa_sh(a0, 1);
        pa2 = mapa_sh(a0, 2);
        pa3 = mapa_sh(a0, 3);
    }
    // consumers: thread t (<192) polls pair t, stages into compact padded slot
    int cslot = (tid < 96) ? tid : (tid + 4);          // +4-float pad between halves
    unsigned poll_a = smem_u32(&hpair[0][tid < DHH ? tid : 0]);

    __syncthreads();
    cluster_sync_all();   // zeroed tagged buffers visible cluster-wide

    // 2-deep gate-preactivation prefetch (load-to-use > DRAM latency); kh=0 lanes only
    float g0 = 0.f, g1 = 0.f;
    if (kh == 0) { g0 = gptr[0]; g1 = gptr[DHH]; }

    const unsigned BUFBYTES = DHH * 8;

    for (int s = 0; s < SS; s++) {
        int cur = s & 1;

        // ---- wait for h_s (tag >= s) and stage value into compact padded array ----
        if (tid < DHH) {
            unsigned a = poll_a + (unsigned)cur * BUFBYTES;
            unsigned long long p = ld_pair(a);
            while ((unsigned)(p >> 32) < (unsigned)s) p = ld_pair(a);
            sh_h[cur][cslot] = __uint_as_float((unsigned)p);
        }
        __syncthreads();                                  // all h_s values staged (ONE bar/step)

        float g2 = 0.f;
        if (kh == 0) {
            int sp = (s + 2 < SS) ? s + 2 : SS - 1;
            g2 = gptr[(size_t)sp * DHH];
        }

        // ---- recurrent matvec: conflict-free dual-broadcast LDS.128 ----
        float2 a0 = make_float2(0.f, 0.f), a1 = a0, a2 = a0, a3 = a0;
        const float4* hp = (const float4*)&sh_h[cur][kh * HPAD];
#pragma unroll
        for (int i = 0; i < 24; i += 2) {
            float4 h0 = hp[i], h1 = hp[i + 1];
            a0 = ffma2(make_float2(h0.x, h0.y), w[2 * i],     a0);
            a1 = ffma2(make_float2(h0.z, h0.w), w[2 * i + 1], a1);
            a2 = ffma2(make_float2(h1.x, h1.y), w[2 * i + 2], a2);
            a3 = ffma2(make_float2(h1.z, h1.w), w[2 * i + 3], a3);
        }
        float part = ((a0.x + a1.x) + (a0.y + a1.y)) + ((a2.x + a3.x) + (a2.y + a3.y));
        part += __shfl_xor_sync(0xffffffffu, part, 4);   // combine k halves (kh pair)
        if (kh == 0) part += g0 + bv;                    // fold gpre+bias at kh=0 lanes
        g0 = g1; g1 = g2;

        // ---- gather the 4 gate preactivations into lanes 0-3 (warp-local) ----
        float it = __shfl_sync(0xffffffffu, part, e4);        // g=0, kh=0
        float ft = __shfl_sync(0xffffffffu, part, 8 + e4);    // g=1
        float zt = __shfl_sync(0xffffffffu, part, 16 + e4);   // g=2
        float ot = __shfl_sync(0xffffffffu, part, 24 + e4);   // g=3

        // ---- gating in registers (lanes 0-3 of each warp own 4 elements) ----
        if (lane < 4) {
            float fm = ft + m_r;
            float mn = fmaxf(fm, it);
            float ia = __expf(it - mn);
            float fa = __expf(fm - mn);
            float th = 1.f - 2.f / (__expf(2.f * zt) + 1.f);       // tanh
            float cn = fa * c_r + ia * th;
            float nn = fa * n_r + ia;
            float hv = cn / ((1.f + __expf(-ot)) * nn);            // sigmoid(ot)*cn/nn
            c_r = cn; n_r = nn; m_r = mn;

            // ship {value, tag=s+1} as one atomic 8B store to all 4 ranks
            unsigned long long p =
                ((unsigned long long)(unsigned)(s + 1) << 32) | (unsigned long long)__float_as_uint(hv);
            unsigned off = (unsigned)((s + 1) & 1) * BUFBYTES;
            st_pair_cluster(pa0 + off, p);
            st_pair_cluster(pa1 + off, p);
            st_pair_cluster(pa2 + off, p);
            st_pair_cluster(pa3 + off, p);

            ybase[(size_t)s * DD + eg] = hv;          // pre-LN output
        }
        // no trailing bar: next iteration's poll+bar provides the sync
    }

    cluster_sync_all();   // don't exit while peer stores may be in flight
}

// ---------------- 4) multi-head layernorm ----------------
__global__ __launch_bounds__(256) void ln_kernel(const float* __restrict__ GS, float* __restrict__ OUT)
{
    int w = blockIdx.x * 8 + (threadIdx.x >> 5);   // (b*S+s)*NH + h
    int lane = threadIdx.x & 31;
    int h = w & 3;
    int bs = w >> 2;
    const float* yp = g_Y + (size_t)bs * DD + h * DHH;

    float v[6], sum = 0.f, sq = 0.f;
#pragma unroll
    for (int i = 0; i < 6; i++) {
        v[i] = yp[i * 32 + lane];
        sum += v[i];
        sq  = fmaf(v[i], v[i], sq);
    }
#pragma unroll
    for (int o = 16; o > 0; o >>= 1) {
        sum += __shfl_xor_sync(0xffffffffu, sum, o);
        sq  += __shfl_xor_sync(0xffffffffu, sq,  o);
    }
    float mean = sum * (1.f / 192.f);
    float var  = sq * (1.f / 192.f) - mean * mean;
    float inv  = rsqrtf(var + 1e-5f);
    float* op = OUT + (size_t)bs * DD + h * DHH;
#pragma unroll
    for (int i = 0; i < 6; i++)
        op[i * 32 + lane] = (v[i] - mean) * inv * GS[h * DHH + i * 32 + lane];
}

// ---------------- launch ----------------
extern "C" void kernel_launch(void* const* d_in, const int* in_sizes, int n_in,
                              void* d_out, int out_size)
{
    const float* x     = (const float*)d_in[0];
    const float* ck    = (const float*)d_in[1];
    const float* cb    = (const float*)d_in[2];
    const float* Wi    = (const float*)d_in[3];
    const float* Wf    = (const float*)d_in[4];
    const float* Wz    = (const float*)d_in[5];
    const float* Wo    = (const float*)d_in[6];
    const float* R     = (const float*)d_in[7];
    const float* cbias = (const float*)d_in[8];
    const float* gs    = (const float*)d_in[9];
    float* out = (float*)d_out;

    conv_swish_kernel<<<(BB * SS * DD + 255) / 256, 256>>>(x, ck, cb);
    gemm_gates_kernel<<<dim3(SS / GBM, DHH / GBN, BB * NHH * 4), 256>>>(x, Wi, Wf, Wz, Wo);
    scan_kernel<<<BB * NHH * 4, 384>>>(R, cbias);
    ln_kernel<<<(BB * SS * NHH) / 8, 256>>>(gs, out);
}

// round 16
// speedup vs baseline: 1.9073x; 1.0801x over previous
#include <cuda_runtime.h>
#include <cstdint>

#define BB  4
#define SS  2048
#define DD  768
#define NHH 4
#define DHH 192
#define KW  4

// ---------------- scratch (device globals; no allocation allowed) ----------------
__device__ float g_XC[(size_t)BB * SS * DD];                    // conv+swish output
__device__ float g_G[(size_t)BB * NHH * 4 * SS * DHH];          // gate preactivations [z][s][e]
__device__ float g_Y[(size_t)BB * SS * DD];                     // scan output (pre-LN)
__device__ unsigned g_prog[64];                                 // rows of g_G[z] completed

// ---------------- small PTX helpers ----------------
__device__ __forceinline__ unsigned smem_u32(const void* p) {
    return (unsigned)__cvta_generic_to_shared(p);
}
__device__ __forceinline__ unsigned mapa_sh(unsigned addr, unsigned rank) {
    unsigned r;
    asm("mapa.shared::cluster.u32 %0, %1, %2;" : "=r"(r) : "r"(addr), "r"(rank));
    return r;
}
// single 8B relaxed store to a (possibly remote) cluster smem address
__device__ __forceinline__ void st_pair_cluster(unsigned addr, unsigned long long p) {
    asm volatile("st.relaxed.cluster.shared::cluster.b64 [%0], %1;"
                 :: "r"(addr), "l"(p) : "memory");
}
// 8B relaxed load from local smem
__device__ __forceinline__ unsigned long long ld_pair(unsigned addr) {
    unsigned long long p;
    asm volatile("ld.relaxed.cluster.shared::cta.b64 %0, [%1];"
                 : "=l"(p) : "r"(addr) : "memory");
    return p;
}
__device__ __forceinline__ unsigned ld_acq_gpu(const unsigned* p) {
    unsigned v;
    asm volatile("ld.acquire.gpu.global.u32 %0, [%1];" : "=r"(v) : "l"(p) : "memory");
    return v;
}
__device__ __forceinline__ void cluster_sync_all() {
    asm volatile("barrier.cluster.arrive.aligned;" ::: "memory");
    asm volatile("barrier.cluster.wait.aligned;" ::: "memory");
}
// packed dual fp32 FMA (Blackwell f32x2)
__device__ __forceinline__ float2 ffma2(float2 a, float2 b, float2 c) {
    float2 d;
    asm("fma.rn.f32x2 %0, %1, %2, %3;"
        : "=l"(reinterpret_cast<unsigned long long&>(d))
        : "l"(reinterpret_cast<unsigned long long&>(a)),
          "l"(reinterpret_cast<unsigned long long&>(b)),
          "l"(reinterpret_cast<unsigned long long&>(c)));
    return d;
}
// duplicate a scalar into both halves of an f32x2
__device__ __forceinline__ float2 dup2(float a) {
    float2 d;
    asm("mov.b64 %0, {%1, %1};"
        : "=l"(reinterpret_cast<unsigned long long&>(d)) : "f"(a));
    return d;
}

// ---------------- 1) causal depthwise conv + swish (also resets g_prog) ---------
__global__ __launch_bounds__(256) void conv_swish_kernel(
    const float* __restrict__ X, const float* __restrict__ CK, const float* __restrict__ CB)
{
    if (blockIdx.x == 0 && threadIdx.x < 64) g_prog[threadIdx.x] = 0;   // replay-safe reset
    int idx = blockIdx.x * 256 + threadIdx.x;
    if (idx >= BB * SS * DD) return;
    int d  = idx % DD;
    int bs = idx / DD;
    int s  = bs % SS;
    float acc = CB[d];
#pragma unroll
    for (int j = 0; j < KW; j++) {
        int sp = s + j - (KW - 1);
        if (sp >= 0) acc = fmaf(CK[j * DD + d], X[idx + (j - (KW - 1)) * DD], acc);
    }
    g_XC[idx] = acc / (1.f + __expf(-acc));   // swish
}

// ---------------- 2+3) FUSED: scan clusters + co-resident GEMM producers --------
// Grid = 128 CTAs (32 clusters of 4), 384 threads, 1 CTA/SM -> single wave.
//   bid 0..63  : scan. 16 clusters of 4 CTAs; cluster = one (b,h). CTA rank r
//                owns e in [r*48, r*48+48) of ALL four gates (exactly R11 scan).
//   bid 64..127: GEMM worker for z = bid-64. Computes g_G[z] (2048x192) in
//                ascending 128-row tiles; publishes progress via
//                __threadfence + g_prog[z]. Scan gates its 2-ahead g-prefetch
//                on ld.acquire of g_prog (cached monotonic -> ~free steady-state).
#define HPAD 100        // float offset of kh=1 half in compact array (96 + 4 pad)
#define AS_STRIDE 129   // padded A-tile stride

struct ScanSmem {
    float2 hpair[2][DHH];     // transport: {value, tag}
    float  sh_h[2][2 * HPAD]; // compute: compact values, padded halves
};
struct GemmSmem {
    float As[32 * AS_STRIDE]; // 16.5 KB
    float Bs[32][DHH];        // 24 KB
};
union FusedSmem { ScanSmem scan; GemmSmem gemm; };

__global__ __launch_bounds__(384, 1) __cluster_dims__(4, 1, 1)
void fused_scan_kernel(const float* __restrict__ X,
                       const float* __restrict__ Wi, const float* __restrict__ Wf,
                       const float* __restrict__ Wz, const float* __restrict__ Wo,
                       const float* __restrict__ R, const float* __restrict__ CBIAS)
{
    __shared__ __align__(16) FusedSmem smem_u;
    int tid = threadIdx.x;

    if (blockIdx.x >= 64) {
        // ================= GEMM producer CTA (one z matrix) =================
        int z = blockIdx.x - 64;            // b*16 + h*4 + g
        int b = z >> 4, h = (z >> 2) & 3, g = z & 3;
        const float* A = ((g < 2) ? g_XC : X) + (size_t)b * SS * DD + h * DHH;  // row stride DD
        const float* W = ((g == 0) ? Wi : (g == 1) ? Wf : (g == 2) ? Wz : Wo)
                         + (size_t)h * DHH * DHH;
        float* C = g_G + (size_t)z * SS * DHH;

        float* As = smem_u.gemm.As;
        float (*Bs)[DHH] = smem_u.gemm.Bs;

        int tm = (tid / 24) * 8;            // 16 groups x 8 rows
        int tn = (tid % 24) * 8;            // 24 groups x 8 cols (192)

        for (int m0 = 0; m0 < SS; m0 += 128) {
            float2 acc[8][4];
#pragma unroll
            for (int i = 0; i < 8; i++)
#pragma unroll
                for (int j = 0; j < 4; j++) acc[i][j] = make_float2(0.f, 0.f);

            for (int k0 = 0; k0 < DHH; k0 += 32) {
                // A tile 128x32 (float4), stored transposed As[k][m]
                for (int i4 = tid; i4 < 1024; i4 += 384) {
                    int m = i4 >> 3, kq = i4 & 7;
                    float4 v = *(const float4*)(A + (size_t)(m0 + m) * DD + k0 + kq * 4);
                    As[(kq * 4 + 0) * AS_STRIDE + m] = v.x;
                    As[(kq * 4 + 1) * AS_STRIDE + m] = v.y;
                    As[(kq * 4 + 2) * AS_STRIDE + m] = v.z;
                    As[(kq * 4 + 3) * AS_STRIDE + m] = v.w;
                }
                // B tile 32x192 (float4)
                for (int i4 = tid; i4 < 1536; i4 += 384) {
                    int kk = i4 / 48, nq = i4 % 48;
                    *(float4*)&Bs[kk][nq * 4] = *(const float4*)(W + (size_t)(k0 + kk) * DHH + nq * 4);
                }
                __syncthreads();
#pragma unroll
                for (int k = 0; k < 32; k++) {
                    float2 b2[4];
#pragma unroll
                    for (int j = 0; j < 4; j++) b2[j] = *(const float2*)&Bs[k][tn + 2 * j];
#pragma unroll
                    for (int i = 0; i < 8; i++) {
                        float2 ad = dup2(As[k * AS_STRIDE + tm + i]);
#pragma unroll
                        for (int j = 0; j < 4; j++) acc[i][j] = ffma2(ad, b2[j], acc[i][j]);
                    }
                }
                __syncthreads();
            }
#pragma unroll
            for (int i = 0; i < 8; i++)
#pragma unroll
                for (int j = 0; j < 4; j++)
                    *(float2*)(C + (size_t)(m0 + tm + i) * DHH + tn + 2 * j) = acc[i][j];

            // publish: rows [0, m0+128) of z complete
            __syncthreads();
            if (tid == 0) {
                __threadfence();
                asm volatile("st.relaxed.gpu.global.u32 [%0], %1;"
                             :: "l"(&g_prog[z]), "r"((unsigned)(m0 + 128)) : "memory");
            }
        }
        return;
    }

    // ========================= scan CTA (R11 protocol) =========================
    float2 (*hpair)[DHH] = smem_u.scan.hpair;
    float  (*sh_h)[2 * HPAD] = smem_u.scan.sh_h;

    int cid = blockIdx.x >> 2;     // (b*NH + h)
    int b = cid >> 2;
    int h = cid & 3;
    int r = blockIdx.x & 3;        // cluster rank
    int e0 = r * 48;

    int out = tid >> 1;            // 0..191 : g*48 + j
    int kh  = tid & 1;             // k half
    int g   = out / 48;
    int j   = out % 48;
    int e   = e0 + j;
    int kbase = kh * 96;           // k index of this half

    // register-resident recurrent weights: pairs {R[k][e], R[k+1][e]}
    float2 w[48];
    {
        const float* Rb = R + ((size_t)(g * NHH + h)) * DHH * DHH + e;
#pragma unroll
        for (int i = 0; i < 48; i++) {
            w[i].x = Rb[(size_t)(kbase + 2 * i) * DHH];
            w[i].y = Rb[(size_t)(kbase + 2 * i + 1) * DHH];
        }
    }
    float biasr = CBIAS[g * DD + h * DHH + e];

    const float* gptr = g_G + ((size_t)(cid * 4 + g)) * SS * DHH + e;
    const unsigned* gp = &g_prog[cid * 4 + g];
    float* ybase = g_Y + (size_t)b * SS * DD + h * DHH + e0;

    // per-thread scan state (only meaningful for tid < 48)
    float c_r = 0.f, n_r = 0.f, m_r = 0.f;

    // init transport: value 0, tag 0  (tag 0 == h_0)
    for (int i = tid; i < DHH; i += 384) {
        hpair[0][i] = make_float2(0.f, __uint_as_float(0u));
        hpair[1][i] = make_float2(0.f, __uint_as_float(0u));
    }

    // producers: remote pair addresses (element e0+tid of hpair[0]) on all 4 ranks
    unsigned pa0 = 0, pa1 = 0, pa2 = 0, pa3 = 0;
    if (tid < 48) {
        unsigned a0 = smem_u32(&hpair[0][e0 + tid]);
        pa0 = mapa_sh(a0, 0);
        pa1 = mapa_sh(a0, 1);
        pa2 = mapa_sh(a0, 2);
        pa3 = mapa_sh(a0, 3);
    }
    // consumers: thread t (<192) polls pair t, writes compact slot (padded)
    int cslot = (tid < 96) ? tid : (tid + 4);          // +4-float pad between halves
    unsigned poll_a = smem_u32(&hpair[0][tid < DHH ? tid : 0]);

    __syncthreads();
    cluster_sync_all();   // zeroed tagged buffers visible cluster-wide

    // wait for GEMM rows 0,1 then start 2-deep gate prefetch
    unsigned gdone = ld_acq_gpu(gp);
    while (gdone < 2) gdone = ld_acq_gpu(gp);
    float g0 = gptr[0];
    float g1 = gptr[DHH];

    const unsigned BUFBYTES = DHH * 8;

    for (int s = 0; s < SS; s++) {
        int cur = s & 1;

        // ---- wait for h_s (tag >= s) and copy value into compact padded array ----
        if (tid < DHH) {
            unsigned a = poll_a + (unsigned)cur * BUFBYTES;
            unsigned long long p = ld_pair(a);
            while ((unsigned)(p >> 32) < (unsigned)s) p = ld_pair(a);
            sh_h[cur][cslot] = __uint_as_float((unsigned)p);
        }
        __syncthreads();                                  // all h_s values staged

        // ---- gated 2-ahead gate-preactivation prefetch ----
        int sp = (s + 2 < SS) ? s + 2 : SS - 1;
        unsigned need = (unsigned)((s + 3 < SS) ? s + 3 : SS);
        if (gdone < need) { do { gdone = ld_acq_gpu(gp); } while (gdone < need); }
        float g2 = gptr[(size_t)sp * DHH];

        // ---- recurrent matvec: conflict-free dual-broadcast LDS.128 ----
        float2 a0 = make_float2(0.f, 0.f), a1 = a0, a2 = a0, a3 = a0;
        const float4* hp = (const float4*)&sh_h[cur][kh * HPAD];
#pragma unroll
        for (int i = 0; i < 24; i += 2) {
            float4 h0 = hp[i], h1 = hp[i + 1];
            a0 = ffma2(make_float2(h0.x, h0.y), w[2 * i],     a0);
            a1 = ffma2(make_float2(h0.z, h0.w), w[2 * i + 1], a1);
            a2 = ffma2(make_float2(h1.x, h1.y), w[2 * i + 2], a2);
            a3 = ffma2(make_float2(h1.z, h1.w), w[2 * i + 3], a3);
        }
        float part = ((a0.x + a1.x) + (a0.y + a1.y)) + ((a2.x + a3.x) + (a2.y + a3.y));
        part += __shfl_xor_sync(0xffffffffu, part, 1);   // combine k halves
        if (kh == 0) smem_u.scan.sh_h[0][0] += 0.f;      // (no-op keepalive; optimized out)
        if (kh == 0) { }
        if ((tid & 1) == 0) {
            // store preactivation for gating threads
        }
        // stage preactivation via shared (R11 scheme)
        {
            __shared__ float sh_pre[DHH];
            if (kh == 0) sh_pre[out] = part + g0 + biasr;
            g0 = g1; g1 = g2;
            __syncthreads();                              // sh_pre ready

            // ---- elementwise stabilized exponential gating (local slice) ----
            if (tid < 48) {
                float it = sh_pre[tid];
                float ft = sh_pre[48 + tid];
                float zt = sh_pre[96 + tid];
                float ot = sh_pre[144 + tid];
                float fm = ft + m_r;
                float mn = fmaxf(fm, it);
                float ia = __expf(it - mn);
                float fa = __expf(fm - mn);
                float th = 1.f - 2.f / (__expf(2.f * zt) + 1.f);       // tanh
                float cn = fa * c_r + ia * th;
                float nn = fa * n_r + ia;
                float hv = cn / ((1.f + __expf(-ot)) * nn);            // sigmoid(ot)*cn/nn
                c_r = cn; n_r = nn; m_r = mn;

                // ship {value, tag=s+1} as one atomic 8B store to all 4 ranks
                unsigned long long p =
                    ((unsigned long long)(unsigned)(s + 1) << 32) | (unsigned long long)__float_as_uint(hv);
                unsigned off = (unsigned)((s + 1) & 1) * BUFBYTES;
                st_pair_cluster(pa0 + off, p);
                st_pair_cluster(pa1 + off, p);
                st_pair_cluster(pa2 + off, p);
                st_pair_cluster(pa3 + off, p);

                ybase[(size_t)s * DD + tid] = hv;          // pre-LN output
            }
        }
        // no trailing bar: next iteration's poll+bar provides the sync
    }

    cluster_sync_all();   // don't exit while peer stores may be in flight
}

// ---------------- 4) multi-head layernorm ----------------
__global__ __launch_bounds__(256) void ln_kernel(const float* __restrict__ GS, float* __restrict__ OUT)
{
    int w = blockIdx.x * 8 + (threadIdx.x >> 5);   // (b*S+s)*NH + h
    int lane = threadIdx.x & 31;
    int h = w & 3;
    int bs = w >> 2;
    const float* yp = g_Y + (size_t)bs * DD + h * DHH;

    float v[6], sum = 0.f, sq = 0.f;
#pragma unroll
    for (int i = 0; i < 6; i++) {
        v[i] = yp[i * 32 + lane];
        sum += v[i];
        sq  = fmaf(v[i], v[i], sq);
    }
#pragma unroll
    for (int o = 16; o > 0; o >>= 1) {
        sum += __shfl_xor_sync(0xffffffffu, sum, o);
        sq  += __shfl_xor_sync(0xffffffffu, sq,  o);
    }
    float mean = sum * (1.f / 192.f);
    float var  = sq * (1.f / 192.f) - mean * mean;
    float inv  = rsqrtf(var + 1e-5f);
    float* op = OUT + (size_t)bs * DD + h * DHH;
#pragma unroll
    for (int i = 0; i < 6; i++)
        op[i * 32 + lane] = (v[i] - mean) * inv * GS[h * DHH + i * 32 + lane];
}

// ---------------- launch ----------------
extern "C" void kernel_launch(void* const* d_in, const int* in_sizes, int n_in,
                              void* d_out, int out_size)
{
    const float* x     = (const float*)d_in[0];
    const float* ck    = (const float*)d_in[1];
    const float* cb    = (const float*)d_in[2];
    const float* Wi    = (const float*)d_in[3];
    const float* Wf    = (const float*)d_in[4];
    const float* Wz    = (const float*)d_in[5];
    const float* Wo    = (const float*)d_in[6];
    const float* R     = (const float*)d_in[7];
    const float* cbias = (const float*)d_in[8];
    const float* gs    = (const float*)d_in[9];
    float* out = (float*)d_out;

    conv_swish_kernel<<<(BB * SS * DD + 255) / 256, 256>>>(x, ck, cb);
    fused_scan_kernel<<<128, 384>>>(x, Wi, Wf, Wz, Wo, R, cbias);
    ln_kernel<<<(BB * SS * NHH) / 8, 256>>>(gs, out);
}

// round 17
// speedup vs baseline: 2.0034x; 1.0504x over previous
#include <cuda_runtime.h>
#include <cstdint>

#define BB  4
#define SS  2048
#define DD  768
#define NHH 4
#define DHH 192
#define KW  4

// ---------------- scratch (device globals; no allocation allowed) ----------------
__device__ float g_G[(size_t)BB * NHH * 4 * SS * DHH];          // gate preactivations [z][s][e]
__device__ float g_Y[(size_t)BB * SS * DD];                     // scan output (pre-LN)
__device__ unsigned g_prog[64];                                 // rows of g_G[z] completed
__device__ unsigned g_sdone[64];                                // scan steps completed [cid*4+r]

// ---------------- small PTX helpers ----------------
__device__ __forceinline__ unsigned smem_u32(const void* p) {
    return (unsigned)__cvta_generic_to_shared(p);
}
__device__ __forceinline__ unsigned mapa_sh(unsigned addr, unsigned rank) {
    unsigned r;
    asm("mapa.shared::cluster.u32 %0, %1, %2;" : "=r"(r) : "r"(addr), "r"(rank));
    return r;
}
__device__ __forceinline__ void st_pair_cluster(unsigned addr, unsigned long long p) {
    asm volatile("st.relaxed.cluster.shared::cluster.b64 [%0], %1;"
                 :: "r"(addr), "l"(p) : "memory");
}
__device__ __forceinline__ unsigned long long ld_pair(unsigned addr) {
    unsigned long long p;
    asm volatile("ld.relaxed.cluster.shared::cta.b64 %0, [%1];"
                 : "=l"(p) : "r"(addr) : "memory");
    return p;
}
__device__ __forceinline__ unsigned ld_acq_gpu(const unsigned* p) {
    unsigned v;
    asm volatile("ld.acquire.gpu.global.u32 %0, [%1];" : "=r"(v) : "l"(p) : "memory");
    return v;
}
__device__ __forceinline__ void st_rel_gpu(unsigned* p, unsigned v) {
    asm volatile("st.relaxed.gpu.global.u32 [%0], %1;" :: "l"(p), "r"(v) : "memory");
}
__device__ __forceinline__ void cluster_sync_all() {
    asm volatile("barrier.cluster.arrive.aligned;" ::: "memory");
    asm volatile("barrier.cluster.wait.aligned;" ::: "memory");
}
__device__ __forceinline__ float2 ffma2(float2 a, float2 b, float2 c) {
    float2 d;
    asm("fma.rn.f32x2 %0, %1, %2, %3;"
        : "=l"(reinterpret_cast<unsigned long long&>(d))
        : "l"(reinterpret_cast<unsigned long long&>(a)),
          "l"(reinterpret_cast<unsigned long long&>(b)),
          "l"(reinterpret_cast<unsigned long long&>(c)));
    return d;
}
__device__ __forceinline__ float2 dup2(float a) {
    float2 d;
    asm("mov.b64 %0, {%1, %1};"
        : "=l"(reinterpret_cast<unsigned long long&>(d)) : "f"(a));
    return d;
}
__device__ __forceinline__ float swishf(float x) {
    return x / (1.f + __expf(-x));
}

// ---------------- 0) replay-safe counter reset ----------------
__global__ void init_kernel() {
    if (threadIdx.x < 64) { g_prog[threadIdx.x] = 0; g_sdone[threadIdx.x] = 0; }
}

// ---------------- FUSED: scan clusters + GEMM(+conv) producers + LN consumers ----
// Grid = 128 CTAs (32 clusters of 4), 384 threads, 1 CTA/SM -> single wave.
//   bid 0..63  : scan (R11 protocol; 16 clusters of 4; cluster = one (b,h)).
//                Publishes g_sdone[cid*4+r] every 256 steps.
//   bid 64..127: worker for z = bid-64 = cid*4+g. Phase 1: GEMM g_G[z]
//                (2048x192), conv+swish computed INLINE for g<2; publishes
//                g_prog[z] per 128-row tile. Phase 2: waits on g_sdone and
//                layernorms quarter q=g of cid's rows into OUT.
#define HPAD 100        // float offset of kh=1 half in compact array (96 + 4 pad)
#define AS_STRIDE 129   // padded A-tile stride

struct ScanSmem {
    float2 hpair[2][DHH];     // transport: {value, tag} (remote slices only)
    float  sh_h[2][2 * HPAD]; // compute: compact values, padded halves
};
struct GemmSmem {
    float As[32 * AS_STRIDE];
    float Bs[32][DHH];
};
union FusedSmem { ScanSmem scan; GemmSmem gemm; };

__global__ __launch_bounds__(384, 1) __cluster_dims__(4, 1, 1)
void fused_kernel(const float* __restrict__ X,
                  const float* __restrict__ CK, const float* __restrict__ CB,
                  const float* __restrict__ Wi, const float* __restrict__ Wf,
                  const float* __restrict__ Wz, const float* __restrict__ Wo,
                  const float* __restrict__ R, const float* __restrict__ CBIAS,
                  const float* __restrict__ GS, float* __restrict__ OUT)
{
    __shared__ __align__(16) FusedSmem smem_u;
    __shared__ float sh_pre[DHH];
    int tid = threadIdx.x;

    if (blockIdx.x >= 64) {
        // ================= worker CTA: GEMM (+conv) then LN =================
        int z = blockIdx.x - 64;            // cid*4 + g
        int b = z >> 4, h = (z >> 2) & 3, g = z & 3;
        const float* Xb = X + (size_t)b * SS * DD + h * DHH;    // row stride DD
        const float* W = ((g == 0) ? Wi : (g == 1) ? Wf : (g == 2) ? Wz : Wo)
                         + (size_t)h * DHH * DHH;
        float* C = g_G + (size_t)z * SS * DHH;

        float* As = smem_u.gemm.As;
        float (*Bs)[DHH] = smem_u.gemm.Bs;

        int tm = (tid / 24) * 8;            // 16 groups x 8 rows
        int tn = (tid % 24) * 8;            // 24 groups x 8 cols (192)

        for (int m0 = 0; m0 < SS; m0 += 128) {
            float2 acc[8][4];
#pragma unroll
            for (int i = 0; i < 8; i++)
#pragma unroll
                for (int j = 0; j < 4; j++) acc[i][j] = make_float2(0.f, 0.f);

            for (int k0 = 0; k0 < DHH; k0 += 32) {
                // A tile 128x32 (float4); conv+swish inline for gates i,f
                for (int i4 = tid; i4 < 1024; i4 += 384) {
                    int m = i4 >> 3, kq = i4 & 7;
                    int col = k0 + kq * 4;                      // head-local col
                    const float* xp = Xb + (size_t)(m0 + m) * DD + col;
                    float4 v;
                    if (g < 2) {
                        float4 a4 = *(const float4*)(CB + h * DHH + col);
#pragma unroll
                        for (int j = 0; j < KW; j++) {
                            if (m0 + m - 3 + j >= 0) {
                                float4 xv = *(const float4*)(xp + (j - 3) * DD);
                                float4 cv = *(const float4*)(CK + j * DD + h * DHH + col);
                                a4.x = fmaf(cv.x, xv.x, a4.x);
                                a4.y = fmaf(cv.y, xv.y, a4.y);
                                a4.z = fmaf(cv.z, xv.z, a4.z);
                                a4.w = fmaf(cv.w, xv.w, a4.w);
                            }
                        }
                        v.x = swishf(a4.x); v.y = swishf(a4.y);
                        v.z = swishf(a4.z); v.w = swishf(a4.w);
                    } else {
                        v = *(const float4*)xp;
                    }
                    As[(kq * 4 + 0) * AS_STRIDE + m] = v.x;
                    As[(kq * 4 + 1) * AS_STRIDE + m] = v.y;
                    As[(kq * 4 + 2) * AS_STRIDE + m] = v.z;
                    As[(kq * 4 + 3) * AS_STRIDE + m] = v.w;
                }
                // B tile 32x192 (float4)
                for (int i4 = tid; i4 < 1536; i4 += 384) {
                    int kk = i4 / 48, nq = i4 % 48;
                    *(float4*)&Bs[kk][nq * 4] = *(const float4*)(W + (size_t)(k0 + kk) * DHH + nq * 4);
                }
                __syncthreads();
#pragma unroll
                for (int k = 0; k < 32; k++) {
                    float2 b2[4];
#pragma unroll
                    for (int j = 0; j < 4; j++) b2[j] = *(const float2*)&Bs[k][tn + 2 * j];
#pragma unroll
                    for (int i = 0; i < 8; i++) {
                        float2 ad = dup2(As[k * AS_STRIDE + tm + i]);
#pragma unroll
                        for (int j = 0; j < 4; j++) acc[i][j] = ffma2(ad, b2[j], acc[i][j]);
                    }
                }
                __syncthreads();
            }
#pragma unroll
            for (int i = 0; i < 8; i++)
#pragma unroll
                for (int j = 0; j < 4; j++)
                    *(float2*)(C + (size_t)(m0 + tm + i) * DHH + tn + 2 * j) = acc[i][j];

            __syncthreads();
            if (tid == 0) {
                __threadfence();
                st_rel_gpu(&g_prog[z], (unsigned)(m0 + 128));
            }
        }

        // ---------------- Phase 2: layernorm quarter q = g of cid ----------------
        int cid = z >> 2;
        int q = g;
        unsigned needs = (unsigned)((q + 1) * 512);
#pragma unroll
        for (int rr = 0; rr < 4; rr++)
            while (ld_acq_gpu(&g_sdone[cid * 4 + rr]) < needs) __nanosleep(256);

        int b2i = cid >> 2, h2 = cid & 3;
        int wrp = tid >> 5, lane = tid & 31;
        for (int s = 512 * q + wrp; s < 512 * (q + 1); s += 12) {
            const float* yp = g_Y + ((size_t)(b2i * SS + s)) * DD + h2 * DHH;
            float v[6], sum = 0.f, sq = 0.f;
#pragma unroll
            for (int i = 0; i < 6; i++) {
                v[i] = yp[i * 32 + lane];
                sum += v[i];
                sq  = fmaf(v[i], v[i], sq);
            }
#pragma unroll
            for (int o = 16; o > 0; o >>= 1) {
                sum += __shfl_xor_sync(0xffffffffu, sum, o);
                sq  += __shfl_xor_sync(0xffffffffu, sq,  o);
            }
            float mean = sum * (1.f / 192.f);
            float var  = sq * (1.f / 192.f) - mean * mean;
            float inv  = rsqrtf(var + 1e-5f);
            float* op = OUT + ((size_t)(b2i * SS + s)) * DD + h2 * DHH;
#pragma unroll
            for (int i = 0; i < 6; i++)
                op[i * 32 + lane] = (v[i] - mean) * inv * GS[h2 * DHH + i * 32 + lane];
        }
        return;
    }

    // ========================= scan CTA (R11 protocol) =========================
    float2 (*hpair)[DHH] = smem_u.scan.hpair;
    float  (*sh_h)[2 * HPAD] = smem_u.scan.sh_h;

    int cid = blockIdx.x >> 2;     // (b*NH + h)
    int b = cid >> 2;
    int h = cid & 3;
    int r = blockIdx.x & 3;        // cluster rank
    int e0 = r * 48;

    int out = tid >> 1;            // 0..191 : g*48 + j
    int kh  = tid & 1;             // k half
    int g   = out / 48;
    int j   = out % 48;
    int e   = e0 + j;
    int kbase = kh * 96;           // k index of this half

    // register-resident recurrent weights: pairs {R[k][e], R[k+1][e]}
    float2 w[48];
    {
        const float* Rb = R + ((size_t)(g * NHH + h)) * DHH * DHH + e;
#pragma unroll
        for (int i = 0; i < 48; i++) {
            w[i].x = Rb[(size_t)(kbase + 2 * i) * DHH];
            w[i].y = Rb[(size_t)(kbase + 2 * i + 1) * DHH];
        }
    }
    float biasr = CBIAS[g * DD + h * DHH + e];

    const float* gptr = g_G + ((size_t)(cid * 4 + g)) * SS * DHH + e;
    const unsigned* gp = &g_prog[cid * 4 + g];
    float* ybase = g_Y + (size_t)b * SS * DD + h * DHH + e0;

    // per-thread scan state (only meaningful for tid < 48)
    float c_r = 0.f, n_r = 0.f, m_r = 0.f;

    // init transport + compute buffers (tag 0 == h_0 = 0)
    for (int i = tid; i < DHH; i += 384) {
        hpair[0][i] = make_float2(0.f, __uint_as_float(0u));
        hpair[1][i] = make_float2(0.f, __uint_as_float(0u));
    }
    for (int i = tid; i < 2 * HPAD; i += 384) { sh_h[0][i] = 0.f; sh_h[1][i] = 0.f; }

    // producers (tid<48): remote pair addresses on the 3 OTHER ranks; own slot local
    unsigned pa0 = 0, pa1 = 0, pa2 = 0;
    int own_slot = 0;
    if (tid < 48) {
        int eg = e0 + tid;
        unsigned a0 = smem_u32(&hpair[0][eg]);
        pa0 = mapa_sh(a0, (r + 1) & 3);
        pa1 = mapa_sh(a0, (r + 2) & 3);
        pa2 = mapa_sh(a0, (r + 3) & 3);
        own_slot = (eg < 96) ? eg : eg + 4;
    }
    // consumers: 144 threads poll the 3 remote slices, stage into padded slots
    int cslot = 0;
    unsigned poll_a = 0;
    if (tid < 144) {
        int src = (r + 1 + tid / 48) & 3;
        int egr = src * 48 + (tid % 48);
        cslot = (egr < 96) ? egr : egr + 4;
        poll_a = smem_u32(&hpair[0][egr]);
    }

    __syncthreads();
    cluster_sync_all();   // zeroed tagged buffers visible cluster-wide

    // wait for GEMM rows 0,1 then start 2-deep gate prefetch
    unsigned gdone = ld_acq_gpu(gp);
    while (gdone < 2) gdone = ld_acq_gpu(gp);
    float g0 = gptr[0];
    float g1 = gptr[DHH];

    const unsigned BUFBYTES = DHH * 8;

    for (int s = 0; s < SS; s++) {
        int cur = s & 1;

        // ---- wait for remote h_s slices (tag >= s), stage into compact array ----
        if (tid < 144) {
            unsigned a = poll_a + (unsigned)cur * BUFBYTES;
            unsigned long long p = ld_pair(a);
            while ((unsigned)(p >> 32) < (unsigned)s) p = ld_pair(a);
            sh_h[cur][cslot] = __uint_as_float((unsigned)p);
        }
        __syncthreads();                                  // staged + own-slice writes of s-1 visible

        // publish scan progress for the LN consumers (covers y rows < s)
        if ((s & 255) == 0 && s != 0 && tid == 0) {
            __threadfence();
            st_rel_gpu(&g_sdone[cid * 4 + r], (unsigned)s);
        }

        // ---- gated 2-ahead gate-preactivation prefetch ----
        int sp = (s + 2 < SS) ? s + 2 : SS - 1;
        unsigned need = (unsigned)((s + 3 < SS) ? s + 3 : SS);
        if (gdone < need) { do { gdone = ld_acq_gpu(gp); } while (gdone < need); }
        float g2 = gptr[(size_t)sp * DHH];

        // ---- recurrent matvec: conflict-free dual-broadcast LDS.128 ----
        float2 a0 = make_float2(0.f, 0.f), a1 = a0, a2 = a0, a3 = a0;
        const float4* hp = (const float4*)&sh_h[cur][kh * HPAD];
#pragma unroll
        for (int i = 0; i < 24; i += 2) {
            float4 h0 = hp[i], h1 = hp[i + 1];
            a0 = ffma2(make_float2(h0.x, h0.y), w[2 * i],     a0);
            a1 = ffma2(make_float2(h0.z, h0.w), w[2 * i + 1], a1);
            a2 = ffma2(make_float2(h1.x, h1.y), w[2 * i + 2], a2);
            a3 = ffma2(make_float2(h1.z, h1.w), w[2 * i + 3], a3);
        }
        float part = ((a0.x + a1.x) + (a0.y + a1.y)) + ((a2.x + a3.x) + (a2.y + a3.y));
        part += __shfl_xor_sync(0xffffffffu, part, 1);   // combine k halves
        if (kh == 0) sh_pre[out] = part + g0 + biasr;
        g0 = g1; g1 = g2;
        __syncthreads();                                  // sh_pre ready

        // ---- elementwise stabilized exponential gating (local slice) ----
        if (tid < 48) {
            float it = sh_pre[tid];
            float ft = sh_pre[48 + tid];
            float zt = sh_pre[96 + tid];
            float ot = sh_pre[144 + tid];
            float fm = ft + m_r;
            float mn = fmaxf(fm, it);
            float ia = __expf(it - mn);
            float fa = __expf(fm - mn);
            float th = 1.f - 2.f / (__expf(2.f * zt) + 1.f);       // tanh
            float cn = fa * c_r + ia * th;
            float nn = fa * n_r + ia;
            float hv = cn / ((1.f + __expf(-ot)) * nn);            // sigmoid(ot)*cn/nn
            c_r = cn; n_r = nn; m_r = mn;

            int nxt = (s + 1) & 1;
            sh_h[nxt][own_slot] = hv;                  // own slice: direct local stage
            unsigned long long p =
                ((unsigned long long)(unsigned)(s + 1) << 32) | (unsigned long long)__float_as_uint(hv);
            unsigned off = (unsigned)nxt * BUFBYTES;
            st_pair_cluster(pa0 + off, p);             // 3 peers, fire-and-forget
            st_pair_cluster(pa1 + off, p);
            st_pair_cluster(pa2 + off, p);

            ybase[(size_t)s * DD + tid] = hv;          // pre-LN output
        }
        // no trailing bar: next iteration's poll+bar provides the sync
    }

    // final progress publish (covers all y rows)
    __syncthreads();
    if (tid == 0) {
        __threadfence();
        st_rel_gpu(&g_sdone[cid * 4 + r], (unsigned)SS);
    }
    cluster_sync_all();   // don't exit while peer stores may be in flight
}

// ---------------- launch ----------------
extern "C" void kernel_launch(void* const* d_in, const int* in_sizes, int n_in,
                              void* d_out, int out_size)
{
    const float* x     = (const float*)d_in[0];
    const float* ck    = (const float*)d_in[1];
    const float* cb    = (const float*)d_in[2];
    const float* Wi    = (const float*)d_in[3];
    const float* Wf    = (const float*)d_in[4];
    const float* Wz    = (const float*)d_in[5];
    const float* Wo    = (const float*)d_in[6];
    const float* R     = (const float*)d_in[7];
    const float* cbias = (const float*)d_in[8];
    const float* gs    = (const float*)d_in[9];
    float* out = (float*)d_out;

    init_kernel<<<1, 64>>>();
    fused_kernel<<<128, 384>>>(x, ck, cb, Wi, Wf, Wz, Wo, R, cbias, gs, out);
}